// round 8
// baseline (speedup 1.0000x reference)
#include <cuda_runtime.h>
#include <cstdint>

// LSTM: B=2048, T=4096, I=5, H=10. Gate order i,f,g,o (rows of W_ih/W_hh).
//   gates = x @ W_ih^T + b_ih + b_hh + h @ W_hh^T
//   c = sigmoid(f)*c + sigmoid(i)*tanh(g);  h = sigmoid(o)*tanh(c)
//
// One thread per (batch, hidden unit j); 10-lane groups, 3 batches/warp.
// h exchanged via SMEM duplicated-pair broadcast: each lane STS.64 (h,h),
// one __syncwarp, then 5x LDS.128 deliver all ten (h_k,h_k) f32x2 operands
// directly (no shuffles, no pack MOVs). Double-buffered (256B XOR toggle).
// Packed f32x2 FMA for gate pairs (i,f),(g,o). MUFU.TANH activations with
// sigmoid(x)=0.5+0.5*tanh(x/2), the x/2 folded into pre-scaled weights.

#define BB 2048
#define TT 4096
#define II 5
#define HH 10

typedef unsigned long long u64;

static __device__ __forceinline__ u64 pk2(float a, float b) {
    u64 r;
    asm("mov.b64 %0, {%1, %2};" : "=l"(r) : "f"(a), "f"(b));
    return r;
}
static __device__ __forceinline__ void upk2(u64 v, float& a, float& b) {
    asm("mov.b64 {%0, %1}, %2;" : "=f"(a), "=f"(b) : "l"(v));
}
static __device__ __forceinline__ u64 ffma2(u64 a, u64 b, u64 c) {
    u64 d;
    asm("fma.rn.f32x2 %0, %1, %2, %3;" : "=l"(d) : "l"(a), "l"(b), "l"(c));
    return d;
}
static __device__ __forceinline__ u64 fadd2(u64 a, u64 b) {
    u64 d;
    asm("add.rn.f32x2 %0, %1, %2;" : "=l"(d) : "l"(a), "l"(b));
    return d;
}
// Single-MUFU tanh (MUFU.TANH), sm_75+.
static __device__ __forceinline__ float tanh_x(float x) {
    float y;
    asm("tanh.approx.f32 %0, %1;" : "=f"(y) : "f"(x));
    return y;
}

__global__ void __launch_bounds__(32)
lstm_scan_kernel(const float* __restrict__ x,
                 const float* __restrict__ h0,
                 const float* __restrict__ c0,
                 const float* __restrict__ W_ih,
                 const float* __restrict__ W_hh,
                 const float* __restrict__ b_ih,
                 const float* __restrict__ b_hh,
                 float* __restrict__ out)
{
    // Two 256-byte buffers: per buffer, 3 groups x 20 floats (duplicated h)
    // at 80-byte stride, + 16B pad for the two idle lanes.
    __shared__ float sh[128];

    const int lane = threadIdx.x;
    const int group = (lane < 30) ? (lane / 10) : 0;
    const int j     = (lane < 30) ? (lane - group * 10) : 0;

    int b = blockIdx.x * 3 + group;
    const bool active = (lane < 30) && (b < BB);
    if (b >= BB) b = 0;  // clamp for safe (redundant) loads; store is guarded

    const uint32_t shb = (uint32_t)__cvta_generic_to_shared(sh);
    // Store address: duplicated pair slot (8B per j). Idle lanes -> pad.
    uint32_t saddr = shb + ((lane < 30) ? (uint32_t)(group * 80 + j * 8)
                                        : (uint32_t)(240 + (lane - 30) * 8));
    // Load base: this group's 80-byte duplicated-h region.
    uint32_t lbase = shb + (uint32_t)(group * 80);

    // Gate rows for this hidden unit.
    const int ri = j, rf = HH + j, rg = 2 * HH + j, ro = 3 * HH + j;

    // Register-resident packed weights. Sigmoid gates (i,f,o) pre-scaled by
    // 0.5 so sigmoid(x) = 0.5 + 0.5*tanh(acc).
    u64 wih_if[II], wih_go[II], whh_if[HH], whh_go[HH];
#pragma unroll
    for (int i = 0; i < II; i++) {
        wih_if[i] = pk2(0.5f * W_ih[ri * II + i], 0.5f * W_ih[rf * II + i]);
        wih_go[i] = pk2(       W_ih[rg * II + i], 0.5f * W_ih[ro * II + i]);
    }
#pragma unroll
    for (int k = 0; k < HH; k++) {
        whh_if[k] = pk2(0.5f * W_hh[ri * HH + k], 0.5f * W_hh[rf * HH + k]);
        whh_go[k] = pk2(       W_hh[rg * HH + k], 0.5f * W_hh[ro * HH + k]);
    }
    const u64 bias_if = pk2(0.5f * (b_ih[ri] + b_hh[ri]),
                            0.5f * (b_ih[rf] + b_hh[rf]));
    const u64 bias_go = pk2(        b_ih[rg] + b_hh[rg],
                            0.5f * (b_ih[ro] + b_hh[ro]));

    float h = h0[b * HH + j];
    float c = c0[b * HH + j];

    const float* xb = x + (size_t)b * TT * II;
    float* ob = out + (size_t)b * TT * HH + j;

    // Prefetch x for t=0.
    float xn[II];
#pragma unroll
    for (int i = 0; i < II; i++) xn[i] = xb[i];

#pragma unroll 1
    for (int t = 0; t < TT; ++t) {
        float xc[II];
#pragma unroll
        for (int i = 0; i < II; i++) xc[i] = xn[i];

        // Prefetch next step's x (independent of the recurrent chain).
        {
            const int tn = (t + 1 < TT) ? (t + 1) : t;
            const float* xp = xb + tn * II;
#pragma unroll
            for (int i = 0; i < II; i++) xn[i] = xp[i];
        }

        // ---- h broadcast: duplicated-pair store, sync, 5x LDS.128 ----
        {
            u64 hhp = pk2(h, h);
            asm volatile("st.shared.b64 [%0], %1;"
                         :: "r"(saddr), "l"(hhp) : "memory");
        }
        __syncwarp();
        u64 hp0, hp1, hp2, hp3, hp4, hp5, hp6, hp7, hp8, hp9;
        asm volatile("ld.shared.v2.b64 {%0, %1}, [%2];"
                     : "=l"(hp0), "=l"(hp1) : "r"(lbase) : "memory");
        asm volatile("ld.shared.v2.b64 {%0, %1}, [%2+16];"
                     : "=l"(hp2), "=l"(hp3) : "r"(lbase) : "memory");
        asm volatile("ld.shared.v2.b64 {%0, %1}, [%2+32];"
                     : "=l"(hp4), "=l"(hp5) : "r"(lbase) : "memory");
        asm volatile("ld.shared.v2.b64 {%0, %1}, [%2+48];"
                     : "=l"(hp6), "=l"(hp7) : "r"(lbase) : "memory");
        asm volatile("ld.shared.v2.b64 {%0, %1}, [%2+64];"
                     : "=l"(hp8), "=l"(hp9) : "r"(lbase) : "memory");
        // Toggle double buffer for next step.
        saddr ^= 256u;
        lbase ^= 256u;

        // Split accumulators (even/odd) to shorten the serial FMA chain.
        u64 aif0 = bias_if, aif1 = 0ull;  // 0ull == {0.0f, 0.0f}
        u64 ago0 = bias_go, ago1 = 0ull;

        // Input contribution (fills the LDS latency shadow).
#pragma unroll
        for (int i = 0; i < II; i++) {
            u64 xx = pk2(xc[i], xc[i]);
            if (i & 1) {
                aif1 = ffma2(wih_if[i], xx, aif1);
                ago1 = ffma2(wih_go[i], xx, ago1);
            } else {
                aif0 = ffma2(wih_if[i], xx, aif0);
                ago0 = ffma2(wih_go[i], xx, ago0);
            }
        }

        // Recurrent contribution with duplicated h pairs (no MOVs).
        aif0 = ffma2(whh_if[0], hp0, aif0);  ago0 = ffma2(whh_go[0], hp0, ago0);
        aif1 = ffma2(whh_if[1], hp1, aif1);  ago1 = ffma2(whh_go[1], hp1, ago1);
        aif0 = ffma2(whh_if[2], hp2, aif0);  ago0 = ffma2(whh_go[2], hp2, ago0);
        aif1 = ffma2(whh_if[3], hp3, aif1);  ago1 = ffma2(whh_go[3], hp3, ago1);
        aif0 = ffma2(whh_if[4], hp4, aif0);  ago0 = ffma2(whh_go[4], hp4, ago0);
        aif1 = ffma2(whh_if[5], hp5, aif1);  ago1 = ffma2(whh_go[5], hp5, ago1);
        aif0 = ffma2(whh_if[6], hp6, aif0);  ago0 = ffma2(whh_go[6], hp6, ago0);
        aif1 = ffma2(whh_if[7], hp7, aif1);  ago1 = ffma2(whh_go[7], hp7, ago1);
        aif0 = ffma2(whh_if[8], hp8, aif0);  ago0 = ffma2(whh_go[8], hp8, ago0);
        aif1 = ffma2(whh_if[9], hp9, aif1);  ago1 = ffma2(whh_go[9], hp9, ago1);

        u64 aif = fadd2(aif0, aif1);
        u64 ago = fadd2(ago0, ago1);
        float ai, af, ag, ao;
        upk2(aif, ai, af);   // pre-scaled by 0.5 (sigmoid args)
        upk2(ago, ag, ao);   // ag unscaled (tanh), ao pre-scaled

        // f-gate first: it heads the critical c -> tanh(c) -> h chain.
        const float fg = fmaf(0.5f, tanh_x(af), 0.5f);
        const float ig = fmaf(0.5f, tanh_x(ai), 0.5f);
        const float gg = tanh_x(ag);
        const float og = fmaf(0.5f, tanh_x(ao), 0.5f);

        c = fmaf(fg, c, ig * gg);
        h = og * tanh_x(c);

        if (active) ob[(size_t)t * HH] = h;
    }
}

extern "C" void kernel_launch(void* const* d_in, const int* in_sizes, int n_in,
                              void* d_out, int out_size) {
    (void)in_sizes; (void)n_in; (void)out_size;
    const float* x    = (const float*)d_in[0];
    const float* h0   = (const float*)d_in[1];
    const float* c0   = (const float*)d_in[2];
    const float* W_ih = (const float*)d_in[3];
    const float* W_hh = (const float*)d_in[4];
    const float* b_ih = (const float*)d_in[5];
    const float* b_hh = (const float*)d_in[6];
    float* out = (float*)d_out;

    const int nwarps = (BB + 2) / 3;  // 3 batches per warp
    lstm_scan_kernel<<<nwarps, 32>>>(x, h0, c0, W_ih, W_hh, b_ih, b_hh, out);
}